// round 1
// baseline (speedup 1.0000x reference)
#include <cuda_runtime.h>
#include <cstdint>

// Correctly-rounded fp32 reciprocals of (1 + m/8), m = 0..7 (e4m3 mantissas).
static __constant__ float c_rcp_mant[8] = {
    1.0f,
    (float)(1.0 / 1.125),
    (float)(1.0 / 1.25),
    (float)(1.0 / 1.375),
    (float)(1.0 / 1.5),
    (float)(1.0 / 1.625),
    (float)(1.0 / 1.75),
    (float)(1.0 / 1.875),
};

// Markstein correctly-rounded division: rb must be RN(1/b). 3 FFMA.
__device__ __forceinline__ float div_rn_(float a, float b, float rb) {
    float q0 = a * rb;
    float e  = fmaf(-q0, b, a);
    return fmaf(e, rb, q0);
}

__global__ __launch_bounds__(256)
void actquant_nvfp4_kernel(const float4* __restrict__ in,
                           float4* __restrict__ out,
                           int ngroups) {
    const float GMF = (float)(1.0 / 6.0);  // 0x3E2AAAAB
    const float RGM = 6.0f;                // RN(1/GMF) == 6.0 exactly

    int g = blockIdx.x * blockDim.x + threadIdx.x;
    if (g >= ngroups) return;

    // Load one 16-element group (64 bytes) as 4x float4.
    float4 v[4];
#pragma unroll
    for (int i = 0; i < 4; i++) v[i] = in[(size_t)g * 4 + i];

    float x[16];
#pragma unroll
    for (int i = 0; i < 4; i++) {
        x[4 * i + 0] = v[i].x;
        x[4 * i + 1] = v[i].y;
        x[4 * i + 2] = v[i].z;
        x[4 * i + 3] = v[i].w;
    }

    // Per-group amax.
    float amax = fabsf(x[0]);
#pragma unroll
    for (int i = 1; i < 16; i++) amax = fmaxf(amax, fabsf(x[i]));

    // scale_raw = (amax / gm) / 6, both IEEE-RN divisions.
    float d1   = div_rn_(amax, GMF, RGM);
    float sraw = div_rn_(d1, 6.0f, GMF);

    // Round to e4m3 grid: keep top-3 mantissa bits, round-half-DOWN
    // (matches reference argmin first-index tie-break), clamp to [2^-7, 480].
    unsigned sb  = __float_as_uint(sraw);
    unsigned rem = sb & 0xFFFFFu;
    unsigned res = (sb & ~0xFFFFFu) + ((rem > 0x80000u) ? 0x100000u : 0u);
    res = (res < 0x3C000000u) ? 0x3C000000u : res;  // 2^-7
    res = (res > 0x43F00000u) ? 0x43F00000u : res;  // 480
    float scale = __uint_as_float(res);

    // Correctly-rounded 1/scale: table reciprocal of mantissa, exact 2^-E.
    unsigned mm = (res >> 20) & 7u;
    int      E  = (int)((res >> 23) & 0xFFu) - 127;
    float    rs = __uint_as_float(__float_as_uint(c_rcp_mant[mm]) -
                                  (unsigned)(E << 23));

    float y[16];
#pragma unroll
    for (int i = 0; i < 16; i++) {
        // u = fp32div(fp32div(x, gm), scale), bit-exact.
        float t = div_rn_(x[i], GMF, RGM);
        float u = div_rn_(t, scale, rs);
        float a = fabsf(u);

        // E2M1 bucket map == reference fp16-bit algorithm.
        // Thresholds are fp16-RNE midpoints; all round INTO the bucket (>=).
        float q;
        q = (a >= 0.24993896484375f) ? 0.5f : 0.0f;
        q = (a >= 0.749755859375f)   ? 1.0f : q;
        q = (a >= 1.24951171875f)    ? 1.5f : q;
        q = (a >= 1.74951171875f)    ? 2.0f : q;
        q = (a >= 2.4990234375f)     ? 3.0f : q;
        q = (a >= 3.4990234375f)     ? 4.0f : q;
        q = (a >= 4.998046875f)      ? 6.0f : q;

        // out = RN(RN(scale * q) * gm), sign from u.
        float o = __fmul_rn(__fmul_rn(scale, q), GMF);
        y[i] = __uint_as_float(__float_as_uint(o) |
                               (__float_as_uint(u) & 0x80000000u));
    }

    float4 w[4];
#pragma unroll
    for (int i = 0; i < 4; i++) {
        w[i].x = y[4 * i + 0];
        w[i].y = y[4 * i + 1];
        w[i].z = y[4 * i + 2];
        w[i].w = y[4 * i + 3];
    }
#pragma unroll
    for (int i = 0; i < 4; i++) out[(size_t)g * 4 + i] = w[i];
}

extern "C" void kernel_launch(void* const* d_in, const int* in_sizes, int n_in,
                              void* d_out, int out_size) {
    const float4* in  = (const float4*)d_in[0];
    float4*       out = (float4*)d_out;
    int n = in_sizes[0];
    int ngroups = n / 16;  // GROUP = 16
    int threads = 256;
    int blocks  = (ngroups + threads - 1) / threads;
    actquant_nvfp4_kernel<<<blocks, threads>>>(in, out, ngroups);
}